// round 1
// baseline (speedup 1.0000x reference)
#include <cuda_runtime.h>
#include <cstdint>

// Problem constants
#define Bn 8
#define Hn 224
#define Wn 224
#define Cn 64
#define IN_DIM 576
#define RANKn 100
#define FILTERS 256

// GEMM tile config
#define BM 112
#define BN 128
#define BK 16
#define ASTRIDE 124   // padded row stride for As (16B-aligned, low-conflict)
#define NT 224        // threads per block

// Scratch (allocation-free rule: device globals)
__device__ float g_T[IN_DIM * RANKn];
__device__ float g_W[IN_DIM * FILTERS];

// ---------------------------------------------------------------------------
// Step-dispatched weight folding: g_W = Uproj @ Vproj, where
//   step 0: Uproj = k,         Vproj = aux_Vt
//   step 1: Uproj = aux_U,     Vproj = l_t
//   step 2: Uproj = aux_Unp1@s, Vproj = aux_Vtnp1
// ---------------------------------------------------------------------------
__global__ void build_T(const float* __restrict__ k_,
                        const float* __restrict__ aux_U,
                        const float* __restrict__ aux_Unp1,
                        const float* __restrict__ s,
                        const int* __restrict__ step_p) {
    int idx = blockIdx.x * blockDim.x + threadIdx.x;
    if (idx >= IN_DIM * RANKn) return;
    int st = *step_p;
    float v;
    if (st == 0) {
        v = k_[idx];
    } else if (st == 1) {
        v = aux_U[idx];
    } else {
        int p = idx / RANKn, r = idx % RANKn;
        float acc = 0.f;
        #pragma unroll 4
        for (int q = 0; q < RANKn; ++q)
            acc += aux_Unp1[p * RANKn + q] * s[q * RANKn + r];
        v = acc;
    }
    g_T[idx] = v;
}

__global__ void build_W(const float* __restrict__ aux_Vt,
                        const float* __restrict__ l_t,
                        const float* __restrict__ aux_Vtnp1,
                        const int* __restrict__ step_p) {
    int idx = blockIdx.x * blockDim.x + threadIdx.x;
    if (idx >= IN_DIM * FILTERS) return;
    int st = *step_p;
    const float* V = (st == 0) ? aux_Vt : (st == 1) ? l_t : aux_Vtnp1;
    int p = idx / FILTERS, f = idx % FILTERS;
    float acc = 0.f;
    #pragma unroll 4
    for (int r = 0; r < RANKn; ++r)
        acc += g_T[p * RANKn + r] * V[r * FILTERS + f];
    g_W[idx] = acc;
}

// ---------------------------------------------------------------------------
// Packed fp32x2 helpers (Blackwell FFMA2 path)
// ---------------------------------------------------------------------------
__device__ __forceinline__ unsigned long long pack2(float lo, float hi) {
    unsigned long long r;
    asm("mov.b64 %0, {%1, %2};" : "=l"(r) : "f"(lo), "f"(hi));
    return r;
}
__device__ __forceinline__ void fma2(unsigned long long& d,
                                     unsigned long long a,
                                     unsigned long long b) {
    asm("fma.rn.f32x2 %0, %1, %2, %0;" : "+l"(d) : "l"(a), "l"(b));
}
__device__ __forceinline__ void unpack2(unsigned long long v, float& lo, float& hi) {
    asm("mov.b64 {%0, %1}, %2;" : "=f"(lo), "=f"(hi) : "l"(v));
}

// ---------------------------------------------------------------------------
// Main implicit-GEMM conv: out[b,h,w,f] = relu( sum_p patch[p]*g_W[p][f] + bias )
// Grid: (2 w-tiles, 224 h, 8 b * 2 n-tiles). Block: 224 threads, 8x8 micro-tile.
// ---------------------------------------------------------------------------
__global__ void __launch_bounds__(NT, 2)
conv_main(const float* __restrict__ x,
          const float* __restrict__ bias_b,
          const float* __restrict__ bias_aux,
          const int* __restrict__ step_p,
          float* __restrict__ out) {
    __shared__ __align__(16) float As[BK][ASTRIDE];
    __shared__ __align__(16) float Bs[BK][BN];

    const int wt = blockIdx.x;       // 0..1
    const int h  = blockIdx.y;       // 0..223
    const int bz = blockIdx.z;       // b*2 + nt
    const int b  = bz >> 1;
    const int nt = bz & 1;
    const int w0 = wt * BM;
    const int n0 = nt * BN;

    const int tid = threadIdx.x;
    const int tni = tid & 15;        // 0..15 (N groups of 8)
    const int tmi = tid >> 4;        // 0..13 (M groups of 8)

    const float* bias = (*step_p == 2) ? bias_b : bias_aux;

    unsigned long long acc[8][4];
    #pragma unroll
    for (int i = 0; i < 8; ++i)
        #pragma unroll
        for (int j = 0; j < 4; ++j) acc[i][j] = 0ull;   // (+0.0f, +0.0f)

    const size_t xbase_b = (size_t)b * (Hn * Wn * Cn);

    for (int ko = 0; ko < IN_DIM / BK; ++ko) {          // 36 iterations
        const int tap = ko >> 2;                        // (kh,kw) tap 0..8
        const int c0  = (ko & 3) << 4;                  // channel offset 0/16/32/48
        const int dh  = tap / 3 - 1;
        const int dw  = tap % 3 - 1;
        const int hh  = h + dh;
        const bool hok = ((unsigned)hh < (unsigned)Hn);

        // Load A tile: 112 pixels x 16 channels (448 float4, 2 per thread)
        #pragma unroll
        for (int l = 0; l < 2; ++l) {
            int idx = tid + l * NT;         // 0..447
            int m = idx >> 2;
            int q = idx & 3;
            int ww = w0 + m + dw;
            float4 v = make_float4(0.f, 0.f, 0.f, 0.f);
            if (hok && (unsigned)ww < (unsigned)Wn) {
                v = *reinterpret_cast<const float4*>(
                        x + xbase_b + ((size_t)hh * Wn + ww) * Cn + c0 + q * 4);
            }
            As[q * 4 + 0][m] = v.x;
            As[q * 4 + 1][m] = v.y;
            As[q * 4 + 2][m] = v.z;
            As[q * 4 + 3][m] = v.w;
        }
        // Load B tile: 16 x 128 (512 float4)
        for (int idx = tid; idx < (BK * BN) / 4; idx += NT) {
            int kk = idx >> 5;
            int f4 = idx & 31;
            float4 v = *reinterpret_cast<const float4*>(
                    g_W + (size_t)(ko * BK + kk) * FILTERS + n0 + f4 * 4);
            *reinterpret_cast<float4*>(&Bs[kk][f4 * 4]) = v;
        }
        __syncthreads();

        #pragma unroll
        for (int kk = 0; kk < BK; ++kk) {
            float4 a0 = *reinterpret_cast<const float4*>(&As[kk][tmi * 8]);
            float4 a1 = *reinterpret_cast<const float4*>(&As[kk][tmi * 8 + 4]);
            // B pairs straight from shared memory as 64-bit (n, n+1)
            const unsigned long long* bsp =
                reinterpret_cast<const unsigned long long*>(&Bs[kk][tni * 8]);
            unsigned long long bp0 = bsp[0];
            unsigned long long bp1 = bsp[1];
            unsigned long long bp2 = bsp[2];
            unsigned long long bp3 = bsp[3];
            float av[8] = {a0.x, a0.y, a0.z, a0.w, a1.x, a1.y, a1.z, a1.w};
            #pragma unroll
            for (int i = 0; i < 8; ++i) {
                unsigned long long ap = pack2(av[i], av[i]);
                fma2(acc[i][0], ap, bp0);
                fma2(acc[i][1], ap, bp1);
                fma2(acc[i][2], ap, bp2);
                fma2(acc[i][3], ap, bp3);
            }
        }
        __syncthreads();
    }

    // Epilogue: + bias, relu, store
    const int n_base = n0 + tni * 8;
    #pragma unroll
    for (int i = 0; i < 8; ++i) {
        int w = w0 + tmi * 8 + i;
        const float* bp = bias + ((size_t)h * Wn + w) * FILTERS + n_base;
        float* op = out + (((size_t)(b * Hn + h) * Wn) + w) * FILTERS + n_base;
        float4 bv0 = *reinterpret_cast<const float4*>(bp);
        float4 bv1 = *reinterpret_cast<const float4*>(bp + 4);
        float r[8];
        unpack2(acc[i][0], r[0], r[1]);
        unpack2(acc[i][1], r[2], r[3]);
        unpack2(acc[i][2], r[4], r[5]);
        unpack2(acc[i][3], r[6], r[7]);
        float4 o0, o1;
        o0.x = fmaxf(r[0] + bv0.x, 0.f);
        o0.y = fmaxf(r[1] + bv0.y, 0.f);
        o0.z = fmaxf(r[2] + bv0.z, 0.f);
        o0.w = fmaxf(r[3] + bv0.w, 0.f);
        o1.x = fmaxf(r[4] + bv1.x, 0.f);
        o1.y = fmaxf(r[5] + bv1.y, 0.f);
        o1.z = fmaxf(r[6] + bv1.z, 0.f);
        o1.w = fmaxf(r[7] + bv1.w, 0.f);
        *reinterpret_cast<float4*>(op)     = o0;
        *reinterpret_cast<float4*>(op + 4) = o1;
    }
}

// ---------------------------------------------------------------------------
// Inputs (metadata order): 0:x 1:k 2:l_t 3:s 4:aux_U 5:aux_Unp1 6:aux_Vt
//                          7:aux_Vtnp1 8:b 9:aux_b 10:step
// ---------------------------------------------------------------------------
extern "C" void kernel_launch(void* const* d_in, const int* in_sizes, int n_in,
                              void* d_out, int out_size) {
    const float* x         = (const float*)d_in[0];
    const float* k_        = (const float*)d_in[1];
    const float* l_t       = (const float*)d_in[2];
    const float* s         = (const float*)d_in[3];
    const float* aux_U     = (const float*)d_in[4];
    const float* aux_Unp1  = (const float*)d_in[5];
    const float* aux_Vt    = (const float*)d_in[6];
    const float* aux_Vtnp1 = (const float*)d_in[7];
    const float* bias_b    = (const float*)d_in[8];
    const float* bias_aux  = (const float*)d_in[9];
    const int*   step_p    = (const int*)d_in[10];
    float* out = (float*)d_out;

    build_T<<<(IN_DIM * RANKn + 255) / 256, 256>>>(k_, aux_U, aux_Unp1, s, step_p);
    build_W<<<(IN_DIM * FILTERS + 255) / 256, 256>>>(aux_Vt, l_t, aux_Vtnp1, step_p);

    dim3 grid(Wn / BM, Hn, Bn * (FILTERS / BN));   // (2, 224, 16)
    conv_main<<<grid, NT>>>(x, bias_b, bias_aux, step_p, out);
}

// round 3
// speedup vs baseline: 2.5940x; 2.5940x over previous
#include <cuda_runtime.h>
#include <cstdint>

// Problem constants
#define Bn 8
#define Hn 224
#define Wn 224
#define Cn 64
#define IN_DIM 576
#define RANKn 100
#define FILTERS 256
#define HW 50176            // 224*224

// GEMM tiling
#define CTA_M 256
#define CTA_N 128
#define BK 32
#define NT 256
#define KITERS (IN_DIM / BK)        // 18
#define STAGE_BYTES 49152           // A 32KB + B 16KB
#define SM_TOTAL (2 * STAGE_BYTES)  // 96KB

// Scratch (device globals; no allocation allowed)
__device__ float g_T[IN_DIM * RANKn];
__device__ float g_Wt[FILTERS * IN_DIM];   // [n][k], tf32-rounded

// ---------------------------------------------------------------------------
__device__ __forceinline__ uint32_t smem_u32(const void* p) {
    uint32_t a;
    asm("{ .reg .u64 t; cvta.to.shared.u64 t, %1; cvt.u32.u64 %0, t; }"
        : "=r"(a) : "l"(p));
    return a;
}
#define CP_ASYNC(d, s, sz) \
    asm volatile("cp.async.cg.shared.global [%0], [%1], 16, %2;" \
                 :: "r"(d), "l"(s), "r"(sz))
#define CP_ASYNC16(d, s) \
    asm volatile("cp.async.cg.shared.global [%0], [%1], 16;" :: "r"(d), "l"(s))
#define CP_COMMIT() asm volatile("cp.async.commit_group;" ::: "memory")
#define CP_WAIT1()  asm volatile("cp.async.wait_group 1;" ::: "memory")
#define CP_WAIT0()  asm volatile("cp.async.wait_group 0;" ::: "memory")

#define LDSM_X4(r0, r1, r2, r3, a) \
    asm volatile("ldmatrix.sync.aligned.m8n8.x4.shared.b16 {%0,%1,%2,%3}, [%4];" \
                 : "=r"(r0), "=r"(r1), "=r"(r2), "=r"(r3) : "r"(a))

#define MMA_TF32(c, a, b0, b1)                                              \
    asm volatile("mma.sync.aligned.m16n8k8.row.col.f32.tf32.tf32.f32 "      \
                 "{%0,%1,%2,%3}, {%4,%5,%6,%7}, {%8,%9}, {%0,%1,%2,%3};"    \
                 : "+f"((c)[0]), "+f"((c)[1]), "+f"((c)[2]), "+f"((c)[3])   \
                 : "r"((a)[0]), "r"((a)[1]), "r"((a)[2]), "r"((a)[3]),      \
                   "r"(b0), "r"(b1))

// ---------------------------------------------------------------------------
// Weight folding preps (step-dispatched on device)
// ---------------------------------------------------------------------------
__global__ void build_T(const float* __restrict__ k_,
                        const float* __restrict__ aux_U,
                        const float* __restrict__ aux_Unp1,
                        const float* __restrict__ s,
                        const int* __restrict__ step_p) {
    int idx = blockIdx.x * blockDim.x + threadIdx.x;
    if (idx >= IN_DIM * RANKn) return;
    int st = *step_p;
    float v;
    if (st == 0) v = k_[idx];
    else if (st == 1) v = aux_U[idx];
    else {
        int p = idx / RANKn, r = idx % RANKn;
        float acc = 0.f;
        #pragma unroll 4
        for (int q = 0; q < RANKn; ++q)
            acc += aux_Unp1[p * RANKn + q] * s[q * RANKn + r];
        v = acc;
    }
    g_T[idx] = v;
}

__global__ void build_Wt(const float* __restrict__ aux_Vt,
                         const float* __restrict__ l_t,
                         const float* __restrict__ aux_Vtnp1,
                         const int* __restrict__ step_p) {
    int idx = blockIdx.x * blockDim.x + threadIdx.x;
    if (idx >= FILTERS * IN_DIM) return;
    int st = *step_p;
    const float* V = (st == 0) ? aux_Vt : (st == 1) ? l_t : aux_Vtnp1;
    int n = idx / IN_DIM, k = idx % IN_DIM;
    float acc = 0.f;
    #pragma unroll 4
    for (int r = 0; r < RANKn; ++r)
        acc += g_T[k * RANKn + r] * V[r * FILTERS + n];
    uint32_t t;
    asm("cvt.rna.tf32.f32 %0, %1;" : "=r"(t) : "f"(acc));
    g_Wt[idx] = __uint_as_float(t);
}

// ---------------------------------------------------------------------------
// Main: tf32 mma.sync implicit-GEMM conv
// CTA: 256 pixels x 128 filters; 8 warps (4M x 2N), warp tile 64x64.
// A smem: 256 rows x 128B (8 x 16B chunks, chunk phys = j ^ (row&7))
// B smem: 128 rows x 128B, same swizzle. ldmatrix.x4 for both operands.
// ---------------------------------------------------------------------------
__global__ void __launch_bounds__(NT, 1)
conv_main(const float* __restrict__ x,
          const float* __restrict__ bias_b,
          const float* __restrict__ bias_aux,
          const int* __restrict__ step_p,
          float* __restrict__ out) {
    extern __shared__ __align__(128) char smem[];
    const int tid  = threadIdx.x;
    const int lane = tid & 31;
    const int wid  = tid >> 5;
    const int mwarp = wid >> 1;       // 0..3
    const int nwarp = wid & 1;        // 0..1
    const int Mbase = blockIdx.x * CTA_M;
    const int Nbase = blockIdx.y * CTA_N;
    const uint32_t sb = smem_u32(smem);

    // Per-thread pixel for A loads (one pixel per thread)
    const int p    = Mbase + tid;
    const int bimg = p / HW;
    const int rem  = p - bimg * HW;
    const int h    = rem / Wn;
    const int w    = rem - h * Wn;
    const int t7   = tid & 7;

    float acc[4][8][4];
    #pragma unroll
    for (int mt = 0; mt < 4; ++mt)
        #pragma unroll
        for (int nt = 0; nt < 8; ++nt)
            #pragma unroll
            for (int q = 0; q < 4; ++q) acc[mt][nt][q] = 0.f;

    // Stage loader
    auto load_stage = [&](int stage, int ko) {
        const int tap = ko >> 1;
        const int c0  = (ko & 1) << 5;
        const int dh  = tap / 3 - 1;
        const int dw  = tap % 3 - 1;
        const int hh  = h + dh;
        const int ww  = w + dw;
        const bool ok = ((unsigned)hh < (unsigned)Hn) && ((unsigned)ww < (unsigned)Wn);
        const float* sp = ok
            ? x + (((size_t)bimg * Hn + hh) * Wn + ww) * Cn + c0
            : x;
        const uint32_t zf = ok ? 16u : 0u;
        const uint32_t dA = sb + stage * STAGE_BYTES + tid * 128;
        #pragma unroll
        for (int j = 0; j < 8; ++j)
            CP_ASYNC(dA + ((j ^ t7) << 4), sp + j * 4, zf);

        const int k0 = ko * BK;
        const uint32_t dB = sb + stage * STAGE_BYTES + 32768;
        #pragma unroll
        for (int l = 0; l < 4; ++l) {
            int idx = l * NT + tid;
            int n = idx >> 3, j = idx & 7;
            const float* bs = g_Wt + (size_t)(Nbase + n) * IN_DIM + k0 + j * 4;
            CP_ASYNC16(dB + n * 128 + ((j ^ (n & 7)) << 4), bs);
        }
    };

    // Fragment addressing (thread-invariant parts)
    const int m7  = lane & 7;
    const int khA = lane >> 4;               // A k-half select
    const int khB = (lane >> 3) & 1;         // B k-half select
    const uint32_t arow = (uint32_t)(mwarp * 64 + (lane & 15)) * 128;
    const uint32_t brow = (uint32_t)(nwarp * 64 + ((lane >> 4) << 3) + m7) * 128;
    uint32_t coffA[4], coffB[4];
    #pragma unroll
    for (int ks = 0; ks < 4; ++ks) {
        coffA[ks] = (uint32_t)(((ks * 2 + khA) ^ m7) << 4);
        coffB[ks] = (uint32_t)(((ks * 2 + khB) ^ m7) << 4);
    }

    load_stage(0, 0);
    CP_COMMIT();

    for (int ko = 0; ko < KITERS; ++ko) {
        if (ko + 1 < KITERS) {
            load_stage((ko + 1) & 1, ko + 1);
            CP_COMMIT();
            CP_WAIT1();
        } else {
            CP_WAIT0();
        }
        __syncthreads();

        const uint32_t As = sb + (ko & 1) * STAGE_BYTES;
        const uint32_t Bs = As + 32768;
        #pragma unroll
        for (int ks = 0; ks < 4; ++ks) {
            uint32_t a[4][4];
            #pragma unroll
            for (int mt = 0; mt < 4; ++mt)
                LDSM_X4(a[mt][0], a[mt][1], a[mt][2], a[mt][3],
                        As + arow + mt * (16 * 128) + coffA[ks]);
            uint32_t bf[4][4];
            #pragma unroll
            for (int np = 0; np < 4; ++np)
                LDSM_X4(bf[np][0], bf[np][1], bf[np][2], bf[np][3],
                        Bs + brow + np * (16 * 128) + coffB[ks]);
            #pragma unroll
            for (int mt = 0; mt < 4; ++mt)
                #pragma unroll
                for (int nt = 0; nt < 8; ++nt)
                    MMA_TF32(acc[mt][nt], a[mt],
                             bf[nt >> 1][(nt & 1) * 2],
                             bf[nt >> 1][(nt & 1) * 2 + 1]);
        }
        __syncthreads();
    }

    // Epilogue: bias + relu + store (float2 per fragment half)
    const float* bias = (*step_p == 2) ? bias_b : bias_aux;
    const int g  = lane >> 2;
    const int tq = lane & 3;
    #pragma unroll
    for (int mt = 0; mt < 4; ++mt) {
        const int r0 = Mbase + mwarp * 64 + mt * 16 + g;
        #pragma unroll
        for (int half = 0; half < 2; ++half) {
            const int r = r0 + half * 8;
            const int bi = r / HW;
            const int rr = r - bi * HW;
            const float* bp = bias + (size_t)rr * FILTERS;
            float* op = out + (size_t)r * FILTERS;
            #pragma unroll
            for (int nt = 0; nt < 8; ++nt) {
                const int col = Nbase + nwarp * 64 + nt * 8 + tq * 2;
                const float2 bv = *reinterpret_cast<const float2*>(bp + col);
                float2 o;
                o.x = fmaxf(acc[mt][nt][half * 2 + 0] + bv.x, 0.f);
                o.y = fmaxf(acc[mt][nt][half * 2 + 1] + bv.y, 0.f);
                *reinterpret_cast<float2*>(op + col) = o;
            }
        }
    }
}

// ---------------------------------------------------------------------------
// Inputs: 0:x 1:k 2:l_t 3:s 4:aux_U 5:aux_Unp1 6:aux_Vt 7:aux_Vtnp1
//         8:b 9:aux_b 10:step
// ---------------------------------------------------------------------------
extern "C" void kernel_launch(void* const* d_in, const int* in_sizes, int n_in,
                              void* d_out, int out_size) {
    const float* x         = (const float*)d_in[0];
    const float* k_        = (const float*)d_in[1];
    const float* l_t       = (const float*)d_in[2];
    const float* s         = (const float*)d_in[3];
    const float* aux_U     = (const float*)d_in[4];
    const float* aux_Unp1  = (const float*)d_in[5];
    const float* aux_Vt    = (const float*)d_in[6];
    const float* aux_Vtnp1 = (const float*)d_in[7];
    const float* bias_b    = (const float*)d_in[8];
    const float* bias_aux  = (const float*)d_in[9];
    const int*   step_p    = (const int*)d_in[10];
    float* out = (float*)d_out;

    build_T<<<(IN_DIM * RANKn + 255) / 256, 256>>>(k_, aux_U, aux_Unp1, s, step_p);
    build_Wt<<<(FILTERS * IN_DIM + 255) / 256, 256>>>(aux_Vt, l_t, aux_Vtnp1, step_p);

    static bool cfg_done = false;
    if (!cfg_done) {
        cudaFuncSetAttribute(conv_main,
                             cudaFuncAttributeMaxDynamicSharedMemorySize, SM_TOTAL);
        cfg_done = true;
    }
    dim3 grid((Bn * Hn * Wn) / CTA_M, FILTERS / CTA_N);   // (1568, 2)
    conv_main<<<grid, NT, SM_TOTAL>>>(x, bias_b, bias_aux, step_p, out);
}

// round 4
// speedup vs baseline: 4.3882x; 1.6917x over previous
#include <cuda_runtime.h>
#include <cuda_fp16.h>
#include <cstdint>

// Problem constants
#define Bn 8
#define Hn 224
#define Wn 224
#define Cn 64
#define IN_DIM 576
#define RANKn 100
#define FILTERS 256
#define HW 50176            // 224*224
#define XTOT (Bn * Hn * Wn * Cn)

// GEMM tiling
#define CTA_M 256
#define CTA_N 128
#define BK 64                         // one full 3x3 tap (64 ch) per K-chunk
#define NT 256
#define KITERS (IN_DIM / BK)          // 9
#define STAGE_BYTES 49152             // A 32KB + B 16KB (fp16)
#define NSTAGE 3
#define SM_TOTAL (NSTAGE * STAGE_BYTES)  // 144KB

// Scratch (device globals; no allocation allowed)
__device__ float  g_T[IN_DIM * RANKn];
__device__ __half g_Wh[FILTERS * IN_DIM];   // [n][k] fp16
__device__ __half g_xh[XTOT];               // x in fp16, same layout

// ---------------------------------------------------------------------------
__device__ __forceinline__ uint32_t smem_u32(const void* p) {
    uint32_t a;
    asm("{ .reg .u64 t; cvta.to.shared.u64 t, %1; cvt.u32.u64 %0, t; }"
        : "=r"(a) : "l"(p));
    return a;
}
#define CP_ASYNC_Z(d, s, sz) \
    asm volatile("cp.async.cg.shared.global [%0], [%1], 16, %2;" \
                 :: "r"(d), "l"(s), "r"(sz))
#define CP_ASYNC16(d, s) \
    asm volatile("cp.async.cg.shared.global [%0], [%1], 16;" :: "r"(d), "l"(s))
#define CP_COMMIT() asm volatile("cp.async.commit_group;" ::: "memory")
#define CP_WAIT(n)  asm volatile("cp.async.wait_group %0;" :: "n"(n) : "memory")

#define LDSM_X4(r0, r1, r2, r3, a) \
    asm volatile("ldmatrix.sync.aligned.m8n8.x4.shared.b16 {%0,%1,%2,%3}, [%4];" \
                 : "=r"(r0), "=r"(r1), "=r"(r2), "=r"(r3) : "r"(a))

#define MMA_F16(c, a, b0, b1)                                               \
    asm volatile("mma.sync.aligned.m16n8k16.row.col.f32.f16.f16.f32 "       \
                 "{%0,%1,%2,%3}, {%4,%5,%6,%7}, {%8,%9}, {%0,%1,%2,%3};"    \
                 : "+f"((c)[0]), "+f"((c)[1]), "+f"((c)[2]), "+f"((c)[3])   \
                 : "r"((a)[0]), "r"((a)[1]), "r"((a)[2]), "r"((a)[3]),      \
                   "r"(b0), "r"(b1))

// ---------------------------------------------------------------------------
// Prep kernels
// ---------------------------------------------------------------------------
__global__ void build_T(const float* __restrict__ k_,
                        const float* __restrict__ aux_U,
                        const float* __restrict__ aux_Unp1,
                        const float* __restrict__ s,
                        const int* __restrict__ step_p) {
    int idx = blockIdx.x * blockDim.x + threadIdx.x;
    if (idx >= IN_DIM * RANKn) return;
    int st = *step_p;
    float v;
    if (st == 0) v = k_[idx];
    else if (st == 1) v = aux_U[idx];
    else {
        int p = idx / RANKn, r = idx % RANKn;
        float acc = 0.f;
        #pragma unroll 4
        for (int q = 0; q < RANKn; ++q)
            acc += aux_Unp1[p * RANKn + q] * s[q * RANKn + r];
        v = acc;
    }
    g_T[idx] = v;
}

__global__ void build_Wh(const float* __restrict__ aux_Vt,
                         const float* __restrict__ l_t,
                         const float* __restrict__ aux_Vtnp1,
                         const int* __restrict__ step_p) {
    int idx = blockIdx.x * blockDim.x + threadIdx.x;
    if (idx >= FILTERS * IN_DIM) return;
    int st = *step_p;
    const float* V = (st == 0) ? aux_Vt : (st == 1) ? l_t : aux_Vtnp1;
    int n = idx / IN_DIM, k = idx % IN_DIM;
    float acc = 0.f;
    #pragma unroll 4
    for (int r = 0; r < RANKn; ++r)
        acc += g_T[k * RANKn + r] * V[r * FILTERS + n];
    g_Wh[idx] = __float2half_rn(acc);
}

__global__ void convert_x(const float* __restrict__ x) {
    int idx = blockIdx.x * blockDim.x + threadIdx.x;   // one per 8 floats
    if (idx >= XTOT / 8) return;
    const float4* xp = reinterpret_cast<const float4*>(x) + idx * 2;
    float4 v0 = xp[0], v1 = xp[1];
    __half2 h[4];
    h[0] = __float22half2_rn(make_float2(v0.x, v0.y));
    h[1] = __float22half2_rn(make_float2(v0.z, v0.w));
    h[2] = __float22half2_rn(make_float2(v1.x, v1.y));
    h[3] = __float22half2_rn(make_float2(v1.z, v1.w));
    *reinterpret_cast<uint4*>(g_xh + (size_t)idx * 8) =
        *reinterpret_cast<uint4*>(h);
}

// ---------------------------------------------------------------------------
// Main: fp16 mma.sync implicit-GEMM conv
// CTA: 256 pixels x 128 filters; 8 warps (4M x 2N), warp tile 64x64.
// A smem: 256 rows x 128B (64 fp16), 8x16B chunks, chunk phys = j ^ (row&7)
// B smem: 128 rows x 128B, same swizzle.
// ---------------------------------------------------------------------------
__global__ void __launch_bounds__(NT, 1)
conv_main(const float* __restrict__ bias_b,
          const float* __restrict__ bias_aux,
          const int* __restrict__ step_p,
          float* __restrict__ out) {
    extern __shared__ __align__(128) char smem[];
    const int tid  = threadIdx.x;
    const int lane = tid & 31;
    const int wid  = tid >> 5;
    const int mwarp = wid >> 1;       // 0..3
    const int nwarp = wid & 1;        // 0..1
    const int Mbase = blockIdx.x * CTA_M;
    const int Nbase = blockIdx.y * CTA_N;
    const uint32_t sb = smem_u32(smem);

    // Per-thread pixel for A loads
    const int p    = Mbase + tid;
    const int bimg = p / HW;
    const int rem  = p - bimg * HW;
    const int h    = rem / Wn;
    const int w    = rem - h * Wn;
    const int t7   = tid & 7;

    float acc[4][8][4];
    #pragma unroll
    for (int mt = 0; mt < 4; ++mt)
        #pragma unroll
        for (int nt = 0; nt < 8; ++nt)
            #pragma unroll
            for (int q = 0; q < 4; ++q) acc[mt][nt][q] = 0.f;

    auto load_stage = [&](int ko) {
        const int stage = ko % NSTAGE;
        const int dh = ko / 3 - 1;
        const int dw = ko % 3 - 1;
        const int hh = h + dh;
        const int ww = w + dw;
        const bool ok = ((unsigned)hh < (unsigned)Hn) && ((unsigned)ww < (unsigned)Wn);
        const __half* sp = ok
            ? g_xh + (((size_t)bimg * Hn + hh) * Wn + ww) * Cn
            : g_xh;
        const uint32_t zf = ok ? 16u : 0u;
        const uint32_t dA = sb + stage * STAGE_BYTES + tid * 128;
        #pragma unroll
        for (int j = 0; j < 8; ++j)
            CP_ASYNC_Z(dA + ((j ^ t7) << 4), sp + j * 8, zf);

        const int k0 = ko * BK;
        const uint32_t dB = sb + stage * STAGE_BYTES + 32768;
        #pragma unroll
        for (int l = 0; l < 4; ++l) {
            int idx = l * NT + tid;
            int n = idx >> 3, j = idx & 7;
            const __half* bs = g_Wh + (size_t)(Nbase + n) * IN_DIM + k0 + j * 8;
            CP_ASYNC16(dB + n * 128 + ((j ^ (n & 7)) << 4), bs);
        }
    };

    // Fragment addressing
    const int m7  = lane & 7;
    const int khA = lane >> 4;               // A chunk parity
    const int khB = (lane >> 3) & 1;         // B chunk parity
    const uint32_t arow = (uint32_t)(mwarp * 64 + (lane & 15)) * 128;
    const uint32_t brow = (uint32_t)(nwarp * 64 + ((lane >> 4) << 3) + m7) * 128;
    uint32_t coffA[4], coffB[4];
    #pragma unroll
    for (int ks = 0; ks < 4; ++ks) {
        coffA[ks] = (uint32_t)(((ks * 2 + khA) ^ m7) << 4);
        coffB[ks] = (uint32_t)(((ks * 2 + khB) ^ m7) << 4);
    }

    load_stage(0); CP_COMMIT();
    load_stage(1); CP_COMMIT();

    for (int ko = 0; ko < KITERS; ++ko) {
        if (ko + 2 < KITERS) {
            load_stage(ko + 2);
            CP_COMMIT();
            CP_WAIT(2);
        } else if (ko + 1 < KITERS) {
            CP_WAIT(1);
        } else {
            CP_WAIT(0);
        }
        __syncthreads();

        const uint32_t As = sb + (ko % NSTAGE) * STAGE_BYTES;
        const uint32_t Bs = As + 32768;
        #pragma unroll
        for (int ks = 0; ks < 4; ++ks) {
            uint32_t a[4][4];
            #pragma unroll
            for (int mt = 0; mt < 4; ++mt)
                LDSM_X4(a[mt][0], a[mt][1], a[mt][2], a[mt][3],
                        As + arow + mt * (16 * 128) + coffA[ks]);
            uint32_t bf[4][4];
            #pragma unroll
            for (int np = 0; np < 4; ++np)
                LDSM_X4(bf[np][0], bf[np][1], bf[np][2], bf[np][3],
                        Bs + brow + np * (16 * 128) + coffB[ks]);
            #pragma unroll
            for (int mt = 0; mt < 4; ++mt)
                #pragma unroll
                for (int nt = 0; nt < 8; ++nt)
                    MMA_F16(acc[mt][nt], a[mt],
                            bf[nt >> 1][(nt & 1) * 2],
                            bf[nt >> 1][(nt & 1) * 2 + 1]);
        }
        __syncthreads();
    }

    // Epilogue: bias + relu + store
    const float* bias = (*step_p == 2) ? bias_b : bias_aux;
    const int g  = lane >> 2;
    const int tq = lane & 3;
    #pragma unroll
    for (int mt = 0; mt < 4; ++mt) {
        const int r0 = Mbase + mwarp * 64 + mt * 16 + g;
        #pragma unroll
        for (int half = 0; half < 2; ++half) {
            const int r = r0 + half * 8;
            const int bi = r / HW;
            const int rr = r - bi * HW;
            const float* bp = bias + (size_t)rr * FILTERS;
            float* op = out + (size_t)r * FILTERS;
            #pragma unroll
            for (int nt = 0; nt < 8; ++nt) {
                const int col = Nbase + nwarp * 64 + nt * 8 + tq * 2;
                const float2 bv = *reinterpret_cast<const float2*>(bp + col);
                float2 o;
                o.x = fmaxf(acc[mt][nt][half * 2 + 0] + bv.x, 0.f);
                o.y = fmaxf(acc[mt][nt][half * 2 + 1] + bv.y, 0.f);
                *reinterpret_cast<float2*>(op + col) = o;
            }
        }
    }
}

// ---------------------------------------------------------------------------
// Inputs: 0:x 1:k 2:l_t 3:s 4:aux_U 5:aux_Unp1 6:aux_Vt 7:aux_Vtnp1
//         8:b 9:aux_b 10:step
// ---------------------------------------------------------------------------
extern "C" void kernel_launch(void* const* d_in, const int* in_sizes, int n_in,
                              void* d_out, int out_size) {
    const float* x         = (const float*)d_in[0];
    const float* k_        = (const float*)d_in[1];
    const float* l_t       = (const float*)d_in[2];
    const float* s         = (const float*)d_in[3];
    const float* aux_U     = (const float*)d_in[4];
    const float* aux_Unp1  = (const float*)d_in[5];
    const float* aux_Vt    = (const float*)d_in[6];
    const float* aux_Vtnp1 = (const float*)d_in[7];
    const float* bias_b    = (const float*)d_in[8];
    const float* bias_aux  = (const float*)d_in[9];
    const int*   step_p    = (const int*)d_in[10];
    float* out = (float*)d_out;

    build_T<<<(IN_DIM * RANKn + 255) / 256, 256>>>(k_, aux_U, aux_Unp1, s, step_p);
    build_Wh<<<(FILTERS * IN_DIM + 255) / 256, 256>>>(aux_Vt, l_t, aux_Vtnp1, step_p);
    convert_x<<<(XTOT / 8 + 255) / 256, 256>>>(x);

    static bool cfg_done = false;
    if (!cfg_done) {
        cudaFuncSetAttribute(conv_main,
                             cudaFuncAttributeMaxDynamicSharedMemorySize, SM_TOTAL);
        cfg_done = true;
    }
    dim3 grid((Bn * Hn * Wn) / CTA_M, FILTERS / CTA_N);   // (1568, 2)
    conv_main<<<grid, NT, SM_TOTAL>>>(bias_b, bias_aux, step_p, out);
}

// round 5
// speedup vs baseline: 5.7313x; 1.3061x over previous
#include <cuda_runtime.h>
#include <cuda_fp16.h>
#include <cstdint>

// Problem constants
#define Bn 8
#define Hn 224
#define Wn 224
#define Cn 64
#define IN_DIM 576
#define RANKn 100
#define FILTERS 256
#define HW 50176            // 224*224
#define XTOT (Bn * Hn * Wn * Cn)

// GEMM tiling
#define CTA_M 256
#define CTA_N 128
#define BK 64                         // one full 3x3 tap (64 ch)
#define NT 512
#define KITERS (IN_DIM / BK)          // 9
#define STAGE_BYTES 49152             // A 32KB + B 16KB (fp16)
#define NSTAGE 4
#define SM_TOTAL (NSTAGE * STAGE_BYTES)  // 192KB

// Scratch (device globals; no allocation allowed)
__device__ float  g_T[IN_DIM * RANKn];
__device__ __half g_Wh[FILTERS * IN_DIM];   // [n][k] fp16
__device__ __half g_xh[XTOT];               // x in fp16, same layout

// ---------------------------------------------------------------------------
__device__ __forceinline__ uint32_t smem_u32(const void* p) {
    uint32_t a;
    asm("{ .reg .u64 t; cvta.to.shared.u64 t, %1; cvt.u32.u64 %0, t; }"
        : "=r"(a) : "l"(p));
    return a;
}
#define CP_ASYNC_Z(d, s, sz) \
    asm volatile("cp.async.cg.shared.global [%0], [%1], 16, %2;" \
                 :: "r"(d), "l"(s), "r"(sz))
#define CP_ASYNC16(d, s) \
    asm volatile("cp.async.cg.shared.global [%0], [%1], 16;" :: "r"(d), "l"(s))
#define CP_COMMIT() asm volatile("cp.async.commit_group;" ::: "memory")
#define CP_WAIT(n)  asm volatile("cp.async.wait_group %0;" :: "n"(n) : "memory")

#define LDSM_X4(r0, r1, r2, r3, a) \
    asm volatile("ldmatrix.sync.aligned.m8n8.x4.shared.b16 {%0,%1,%2,%3}, [%4];" \
                 : "=r"(r0), "=r"(r1), "=r"(r2), "=r"(r3) : "r"(a))

#define MMA_F16(c, a, b0, b1)                                               \
    asm volatile("mma.sync.aligned.m16n8k16.row.col.f32.f16.f16.f32 "       \
                 "{%0,%1,%2,%3}, {%4,%5,%6,%7}, {%8,%9}, {%0,%1,%2,%3};"    \
                 : "+f"((c)[0]), "+f"((c)[1]), "+f"((c)[2]), "+f"((c)[3])   \
                 : "r"((a)[0]), "r"((a)[1]), "r"((a)[2]), "r"((a)[3]),      \
                   "r"(b0), "r"(b1))

// ---------------------------------------------------------------------------
// Prep kernels
// ---------------------------------------------------------------------------
__global__ void build_T(const float* __restrict__ k_,
                        const float* __restrict__ aux_U,
                        const float* __restrict__ aux_Unp1,
                        const float* __restrict__ s,
                        const int* __restrict__ step_p) {
    int idx = blockIdx.x * blockDim.x + threadIdx.x;
    if (idx >= IN_DIM * RANKn) return;
    int st = *step_p;
    float v;
    if (st == 0) v = k_[idx];
    else if (st == 1) v = aux_U[idx];
    else {
        int p = idx / RANKn, r = idx % RANKn;
        float acc = 0.f;
        #pragma unroll 4
        for (int q = 0; q < RANKn; ++q)
            acc += aux_Unp1[p * RANKn + q] * s[q * RANKn + r];
        v = acc;
    }
    g_T[idx] = v;
}

__global__ void build_Wh(const float* __restrict__ aux_Vt,
                         const float* __restrict__ l_t,
                         const float* __restrict__ aux_Vtnp1,
                         const int* __restrict__ step_p) {
    int idx = blockIdx.x * blockDim.x + threadIdx.x;
    if (idx >= FILTERS * IN_DIM) return;
    int st = *step_p;
    const float* V = (st == 0) ? aux_Vt : (st == 1) ? l_t : aux_Vtnp1;
    int n = idx / IN_DIM, k = idx % IN_DIM;
    float acc = 0.f;
    #pragma unroll 4
    for (int r = 0; r < RANKn; ++r)
        acc += g_T[k * RANKn + r] * V[r * FILTERS + n];
    g_Wh[idx] = __float2half_rn(acc);
}

__global__ void convert_x(const float* __restrict__ x) {
    int idx = blockIdx.x * blockDim.x + threadIdx.x;   // one per 8 floats
    if (idx >= XTOT / 8) return;
    const float4* xp = reinterpret_cast<const float4*>(x) + idx * 2;
    float4 v0 = xp[0], v1 = xp[1];
    __half2 h[4];
    h[0] = __float22half2_rn(make_float2(v0.x, v0.y));
    h[1] = __float22half2_rn(make_float2(v0.z, v0.w));
    h[2] = __float22half2_rn(make_float2(v1.x, v1.y));
    h[3] = __float22half2_rn(make_float2(v1.z, v1.w));
    *reinterpret_cast<uint4*>(g_xh + (size_t)idx * 8) =
        *reinterpret_cast<uint4*>(h);
}

// ---------------------------------------------------------------------------
// Main: fp16 mma.sync implicit-GEMM conv
// CTA: 256 pixels x 128 filters; 16 warps (4M x 4N), warp tile 64x32.
// A smem: 256 rows x 128B (64 fp16), chunk phys = j ^ (row&7)
// B smem: 128 rows x 128B, same swizzle. 4-stage cp.async, 1 bar/iter.
// ---------------------------------------------------------------------------
__global__ void __launch_bounds__(NT, 1)
conv_main(const float* __restrict__ bias_b,
          const float* __restrict__ bias_aux,
          const int* __restrict__ step_p,
          float* __restrict__ out) {
    extern __shared__ __align__(128) char smem[];
    const int tid  = threadIdx.x;
    const int lane = tid & 31;
    const int wid  = tid >> 5;
    const int mwarp = wid >> 2;       // 0..3
    const int nwarp = wid & 3;        // 0..3
    const int Mbase = blockIdx.x * CTA_M;
    const int Nbase = blockIdx.y * CTA_N;
    const uint32_t sb = smem_u32(smem);

    // Loader geometry: thread handles rows (l*64 + tid>>3), chunk j = tid&7
    const int jA  = tid & 7;
    const int rA  = tid >> 3;          // 0..63
    int hL[4], wL[4], bL[4];
    #pragma unroll
    for (int l = 0; l < 4; ++l) {
        int p = Mbase + l * 64 + rA;
        int bi = p / HW;
        int rem = p - bi * HW;
        hL[l] = rem / Wn;
        wL[l] = rem - hL[l] * Wn;
        bL[l] = bi;
    }

    float acc[4][4][4];
    #pragma unroll
    for (int mt = 0; mt < 4; ++mt)
        #pragma unroll
        for (int nt = 0; nt < 4; ++nt)
            #pragma unroll
            for (int q = 0; q < 4; ++q) acc[mt][nt][q] = 0.f;

    auto load_stage = [&](int ko) {
        const int stage = ko & 3;
        const int dh = ko / 3 - 1;
        const int dw = ko % 3 - 1;
        const uint32_t dA = sb + stage * STAGE_BYTES;
        #pragma unroll
        for (int l = 0; l < 4; ++l) {
            const int row = l * 64 + rA;
            const int hh = hL[l] + dh;
            const int ww = wL[l] + dw;
            const bool ok = ((unsigned)hh < (unsigned)Hn) &&
                            ((unsigned)ww < (unsigned)Wn);
            const __half* sp = ok
                ? g_xh + (((size_t)bL[l] * Hn + hh) * Wn + ww) * Cn + jA * 8
                : g_xh;
            CP_ASYNC_Z(dA + row * 128 + ((jA ^ (row & 7)) << 4), sp, ok ? 16u : 0u);
        }
        const int k0 = ko * BK;
        const uint32_t dB = dA + 32768;
        #pragma unroll
        for (int l = 0; l < 2; ++l) {
            const int n = l * 64 + rA;
            const __half* bs = g_Wh + (size_t)(Nbase + n) * IN_DIM + k0 + jA * 8;
            CP_ASYNC16(dB + n * 128 + ((jA ^ (n & 7)) << 4), bs);
        }
    };

    // Fragment addressing
    const int m7  = lane & 7;
    const int khA = lane >> 4;               // A chunk parity
    const int khB = (lane >> 3) & 1;         // B chunk parity
    const uint32_t arow = (uint32_t)(mwarp * 64 + (lane & 15)) * 128;
    const uint32_t brow = (uint32_t)(nwarp * 32 + ((lane >> 4) << 3) + m7) * 128;
    uint32_t coffA[4], coffB[4];
    #pragma unroll
    for (int ks = 0; ks < 4; ++ks) {
        coffA[ks] = (uint32_t)(((ks * 2 + khA) ^ m7) << 4);
        coffB[ks] = (uint32_t)(((ks * 2 + khB) ^ m7) << 4);
    }

    load_stage(0); CP_COMMIT();
    load_stage(1); CP_COMMIT();
    load_stage(2); CP_COMMIT();

    for (int ko = 0; ko < KITERS; ++ko) {
        // wait for stage ko, barrier, THEN issue loads for ko+3 (stage ko-1's
        // buffer: safe — the barrier proves all warps finished computing ko-1)
        if (ko <= KITERS - 3)      CP_WAIT(2);
        else if (ko == KITERS - 2) CP_WAIT(1);
        else                       CP_WAIT(0);
        __syncthreads();
        if (ko + 3 < KITERS) { load_stage(ko + 3); CP_COMMIT(); }

        const uint32_t As = sb + (ko & 3) * STAGE_BYTES;
        const uint32_t Bs = As + 32768;
        #pragma unroll
        for (int ks = 0; ks < 4; ++ks) {
            uint32_t a[4][4];
            #pragma unroll
            for (int mt = 0; mt < 4; ++mt)
                LDSM_X4(a[mt][0], a[mt][1], a[mt][2], a[mt][3],
                        As + arow + mt * (16 * 128) + coffA[ks]);
            uint32_t bf[2][4];
            #pragma unroll
            for (int np = 0; np < 2; ++np)
                LDSM_X4(bf[np][0], bf[np][1], bf[np][2], bf[np][3],
                        Bs + brow + np * (16 * 128) + coffB[ks]);
            #pragma unroll
            for (int mt = 0; mt < 4; ++mt)
                #pragma unroll
                for (int nt = 0; nt < 4; ++nt)
                    MMA_F16(acc[mt][nt], a[mt],
                            bf[nt >> 1][(nt & 1) * 2],
                            bf[nt >> 1][(nt & 1) * 2 + 1]);
        }
    }

    // Epilogue: bias + relu + store
    const float* bias = (*step_p == 2) ? bias_b : bias_aux;
    const int g  = lane >> 2;
    const int tq = lane & 3;
    #pragma unroll
    for (int mt = 0; mt < 4; ++mt) {
        const int r0 = Mbase + mwarp * 64 + mt * 16 + g;
        #pragma unroll
        for (int half = 0; half < 2; ++half) {
            const int r = r0 + half * 8;
            const int bi = r / HW;
            const int rr = r - bi * HW;
            const float* bp = bias + (size_t)rr * FILTERS;
            float* op = out + (size_t)r * FILTERS;
            #pragma unroll
            for (int nt = 0; nt < 4; ++nt) {
                const int col = Nbase + nwarp * 32 + nt * 8 + tq * 2;
                const float2 bv = *reinterpret_cast<const float2*>(bp + col);
                float2 o;
                o.x = fmaxf(acc[mt][nt][half * 2 + 0] + bv.x, 0.f);
                o.y = fmaxf(acc[mt][nt][half * 2 + 1] + bv.y, 0.f);
                *reinterpret_cast<float2*>(op + col) = o;
            }
        }
    }
}

// ---------------------------------------------------------------------------
// Inputs: 0:x 1:k 2:l_t 3:s 4:aux_U 5:aux_Unp1 6:aux_Vt 7:aux_Vtnp1
//         8:b 9:aux_b 10:step
// ---------------------------------------------------------------------------
extern "C" void kernel_launch(void* const* d_in, const int* in_sizes, int n_in,
                              void* d_out, int out_size) {
    const float* x         = (const float*)d_in[0];
    const float* k_        = (const float*)d_in[1];
    const float* l_t       = (const float*)d_in[2];
    const float* s         = (const float*)d_in[3];
    const float* aux_U     = (const float*)d_in[4];
    const float* aux_Unp1  = (const float*)d_in[5];
    const float* aux_Vt    = (const float*)d_in[6];
    const float* aux_Vtnp1 = (const float*)d_in[7];
    const float* bias_b    = (const float*)d_in[8];
    const float* bias_aux  = (const float*)d_in[9];
    const int*   step_p    = (const int*)d_in[10];
    float* out = (float*)d_out;

    build_T<<<(IN_DIM * RANKn + 255) / 256, 256>>>(k_, aux_U, aux_Unp1, s, step_p);
    build_Wh<<<(FILTERS * IN_DIM + 255) / 256, 256>>>(aux_Vt, l_t, aux_Vtnp1, step_p);
    convert_x<<<(XTOT / 8 + 255) / 256, 256>>>(x);

    static bool cfg_done = false;
    if (!cfg_done) {
        cudaFuncSetAttribute(conv_main,
                             cudaFuncAttributeMaxDynamicSharedMemorySize, SM_TOTAL);
        cfg_done = true;
    }
    dim3 grid((Bn * Hn * Wn) / CTA_M, FILTERS / CTA_N);   // (1568, 2)
    conv_main<<<grid, NT, SM_TOTAL>>>(bias_b, bias_aux, step_p, out);
}

// round 6
// speedup vs baseline: 6.1747x; 1.0774x over previous
#include <cuda_runtime.h>
#include <cuda_fp16.h>
#include <cstdint>

// Problem constants
#define Bn 8
#define Hn 224
#define Wn 224
#define Cn 64
#define IN_DIM 576
#define RANKn 100
#define FILTERS 256
#define HW 50176            // 224*224
#define XTOT (Bn * Hn * Wn * Cn)

// GEMM tiling
#define CTA_M 128
#define CTA_N 128
#define BK 64                         // one full 3x3 tap (64 ch)
#define NT 256
#define KITERS (IN_DIM / BK)          // 9
#define STAGE_BYTES 32768             // A 16KB + B 16KB (fp16)
#define NSTAGE 3
#define SM_TOTAL (NSTAGE * STAGE_BYTES)  // 96KB -> 2 CTAs/SM

// Scratch (device globals; no allocation allowed)
__device__ float  g_T[IN_DIM * RANKn];
__device__ __half g_Wh[FILTERS * IN_DIM];   // [n][k] fp16
__device__ __half g_xh[XTOT];               // x in fp16, same layout

// ---------------------------------------------------------------------------
__device__ __forceinline__ uint32_t smem_u32(const void* p) {
    uint32_t a;
    asm("{ .reg .u64 t; cvta.to.shared.u64 t, %1; cvt.u32.u64 %0, t; }"
        : "=r"(a) : "l"(p));
    return a;
}
#define CP_ASYNC_Z(d, s, sz) \
    asm volatile("cp.async.cg.shared.global [%0], [%1], 16, %2;" \
                 :: "r"(d), "l"(s), "r"(sz))
#define CP_ASYNC16(d, s) \
    asm volatile("cp.async.cg.shared.global [%0], [%1], 16;" :: "r"(d), "l"(s))
#define CP_COMMIT() asm volatile("cp.async.commit_group;" ::: "memory")
#define CP_WAIT(n)  asm volatile("cp.async.wait_group %0;" :: "n"(n) : "memory")

#define LDSM_X4(r0, r1, r2, r3, a) \
    asm volatile("ldmatrix.sync.aligned.m8n8.x4.shared.b16 {%0,%1,%2,%3}, [%4];" \
                 : "=r"(r0), "=r"(r1), "=r"(r2), "=r"(r3) : "r"(a))

#define MMA_F16(c, a, b0, b1)                                               \
    asm volatile("mma.sync.aligned.m16n8k16.row.col.f32.f16.f16.f32 "       \
                 "{%0,%1,%2,%3}, {%4,%5,%6,%7}, {%8,%9}, {%0,%1,%2,%3};"    \
                 : "+f"((c)[0]), "+f"((c)[1]), "+f"((c)[2]), "+f"((c)[3])   \
                 : "r"((a)[0]), "r"((a)[1]), "r"((a)[2]), "r"((a)[3]),      \
                   "r"(b0), "r"(b1))

// ---------------------------------------------------------------------------
// Prep kernels
// ---------------------------------------------------------------------------
__global__ void build_T(const float* __restrict__ k_,
                        const float* __restrict__ aux_U,
                        const float* __restrict__ aux_Unp1,
                        const float* __restrict__ s,
                        const int* __restrict__ step_p) {
    int idx = blockIdx.x * blockDim.x + threadIdx.x;
    if (idx >= IN_DIM * RANKn) return;
    int st = *step_p;
    float v;
    if (st == 0) v = k_[idx];
    else if (st == 1) v = aux_U[idx];
    else {
        int p = idx / RANKn, r = idx % RANKn;
        float acc = 0.f;
        #pragma unroll 4
        for (int q = 0; q < RANKn; ++q)
            acc += aux_Unp1[p * RANKn + q] * s[q * RANKn + r];
        v = acc;
    }
    g_T[idx] = v;
}

__global__ void build_Wh(const float* __restrict__ aux_Vt,
                         const float* __restrict__ l_t,
                         const float* __restrict__ aux_Vtnp1,
                         const int* __restrict__ step_p) {
    int idx = blockIdx.x * blockDim.x + threadIdx.x;
    if (idx >= FILTERS * IN_DIM) return;
    int st = *step_p;
    const float* V = (st == 0) ? aux_Vt : (st == 1) ? l_t : aux_Vtnp1;
    int n = idx / IN_DIM, k = idx % IN_DIM;
    float acc = 0.f;
    #pragma unroll 4
    for (int r = 0; r < RANKn; ++r)
        acc += g_T[k * RANKn + r] * V[r * FILTERS + n];
    g_Wh[idx] = __float2half_rn(acc);
}

__global__ void convert_x(const float* __restrict__ x) {
    int idx = blockIdx.x * blockDim.x + threadIdx.x;   // one per 8 floats
    if (idx >= XTOT / 8) return;
    const float4* xp = reinterpret_cast<const float4*>(x) + idx * 2;
    float4 v0 = xp[0], v1 = xp[1];
    __half2 h[4];
    h[0] = __float22half2_rn(make_float2(v0.x, v0.y));
    h[1] = __float22half2_rn(make_float2(v0.z, v0.w));
    h[2] = __float22half2_rn(make_float2(v1.x, v1.y));
    h[3] = __float22half2_rn(make_float2(v1.z, v1.w));
    *reinterpret_cast<uint4*>(g_xh + (size_t)idx * 8) =
        *reinterpret_cast<uint4*>(h);
}

// ---------------------------------------------------------------------------
// Main: fp16 mma.sync implicit-GEMM conv
// CTA: 128 pixels x 128 filters; 8 warps (2M x 4N), warp tile 64x32.
// 3-stage cp.async ring, one barrier per K-iter, 2 CTAs/SM.
// ---------------------------------------------------------------------------
__global__ void __launch_bounds__(NT, 2)
conv_main(const float* __restrict__ bias_b,
          const float* __restrict__ bias_aux,
          const int* __restrict__ step_p,
          float* __restrict__ out) {
    extern __shared__ __align__(128) char smem[];
    const int tid  = threadIdx.x;
    const int lane = tid & 31;
    const int wid  = tid >> 5;
    const int mwarp = wid >> 2;       // 0..1
    const int nwarp = wid & 3;        // 0..3
    const int Mbase = blockIdx.x * CTA_M;
    const int Nbase = blockIdx.y * CTA_N;
    const uint32_t sb = smem_u32(smem);

    // Loader geometry: chunk j = tid&7, row group rA = tid>>3 (0..31)
    const int jA  = tid & 7;
    const int rA  = tid >> 3;
    int hL[4], wL[4], bL[4];
    #pragma unroll
    for (int l = 0; l < 4; ++l) {
        int p = Mbase + l * 32 + rA;
        int bi = p / HW;
        int rem = p - bi * HW;
        hL[l] = rem / Wn;
        wL[l] = rem - hL[l] * Wn;
        bL[l] = bi;
    }

    float acc[4][4][4];
    #pragma unroll
    for (int mt = 0; mt < 4; ++mt)
        #pragma unroll
        for (int nt = 0; nt < 4; ++nt)
            #pragma unroll
            for (int q = 0; q < 4; ++q) acc[mt][nt][q] = 0.f;

    auto load_stage = [&](int ko) {
        const int stage = ko % NSTAGE;
        const int dh = ko / 3 - 1;
        const int dw = ko % 3 - 1;
        const uint32_t dA = sb + stage * STAGE_BYTES;
        #pragma unroll
        for (int l = 0; l < 4; ++l) {
            const int row = l * 32 + rA;
            const int hh = hL[l] + dh;
            const int ww = wL[l] + dw;
            const bool ok = ((unsigned)hh < (unsigned)Hn) &&
                            ((unsigned)ww < (unsigned)Wn);
            const __half* sp = ok
                ? g_xh + (((size_t)bL[l] * Hn + hh) * Wn + ww) * Cn + jA * 8
                : g_xh;
            CP_ASYNC_Z(dA + row * 128 + ((jA ^ (row & 7)) << 4), sp, ok ? 16u : 0u);
        }
        const int k0 = ko * BK;
        const uint32_t dB = dA + 16384;
        #pragma unroll
        for (int l = 0; l < 4; ++l) {
            const int n = l * 32 + rA;
            const __half* bs = g_Wh + (size_t)(Nbase + n) * IN_DIM + k0 + jA * 8;
            CP_ASYNC16(dB + n * 128 + ((jA ^ (n & 7)) << 4), bs);
        }
    };

    // Fragment addressing
    const int m7  = lane & 7;
    const int khA = lane >> 4;               // A chunk parity
    const int khB = (lane >> 3) & 1;         // B chunk parity
    const uint32_t arow = (uint32_t)(mwarp * 64 + (lane & 15)) * 128;
    const uint32_t brow = (uint32_t)(nwarp * 32 + ((lane >> 4) << 3) + m7) * 128;
    uint32_t coffA[4], coffB[4];
    #pragma unroll
    for (int ks = 0; ks < 4; ++ks) {
        coffA[ks] = (uint32_t)(((ks * 2 + khA) ^ m7) << 4);
        coffB[ks] = (uint32_t)(((ks * 2 + khB) ^ m7) << 4);
    }

    load_stage(0); CP_COMMIT();
    load_stage(1); CP_COMMIT();

    for (int ko = 0; ko < KITERS; ++ko) {
        if (ko < KITERS - 1) CP_WAIT(1);
        else                 CP_WAIT(0);
        __syncthreads();
        if (ko + 2 < KITERS) { load_stage(ko + 2); CP_COMMIT(); }

        const uint32_t As = sb + (ko % NSTAGE) * STAGE_BYTES;
        const uint32_t Bs = As + 16384;

        // Hoist ALL B fragments for this K-iter (8 ldsm.x4 -> 32 regs)
        uint32_t bfa[4][2][4];
        #pragma unroll
        for (int ks = 0; ks < 4; ++ks)
            #pragma unroll
            for (int np = 0; np < 2; ++np)
                LDSM_X4(bfa[ks][np][0], bfa[ks][np][1],
                        bfa[ks][np][2], bfa[ks][np][3],
                        Bs + brow + np * (16 * 128) + coffB[ks]);

        #pragma unroll
        for (int ks = 0; ks < 4; ++ks) {
            uint32_t a[4][4];
            #pragma unroll
            for (int mt = 0; mt < 4; ++mt)
                LDSM_X4(a[mt][0], a[mt][1], a[mt][2], a[mt][3],
                        As + arow + mt * (16 * 128) + coffA[ks]);
            #pragma unroll
            for (int mt = 0; mt < 4; ++mt)
                #pragma unroll
                for (int nt = 0; nt < 4; ++nt)
                    MMA_F16(acc[mt][nt], a[mt],
                            bfa[ks][nt >> 1][(nt & 1) * 2],
                            bfa[ks][nt >> 1][(nt & 1) * 2 + 1]);
        }
    }

    // Epilogue: bias + relu + store
    const float* bias = (*step_p == 2) ? bias_b : bias_aux;
    const int g  = lane >> 2;
    const int tq = lane & 3;
    #pragma unroll
    for (int mt = 0; mt < 4; ++mt) {
        const int r0 = Mbase + mwarp * 64 + mt * 16 + g;
        #pragma unroll
        for (int half = 0; half < 2; ++half) {
            const int r = r0 + half * 8;
            const int bi = r / HW;
            const int rr = r - bi * HW;
            const float* bp = bias + (size_t)rr * FILTERS;
            float* op = out + (size_t)r * FILTERS;
            #pragma unroll
            for (int nt = 0; nt < 4; ++nt) {
                const int col = Nbase + nwarp * 32 + nt * 8 + tq * 2;
                const float2 bv = *reinterpret_cast<const float2*>(bp + col);
                float2 o;
                o.x = fmaxf(acc[mt][nt][half * 2 + 0] + bv.x, 0.f);
                o.y = fmaxf(acc[mt][nt][half * 2 + 1] + bv.y, 0.f);
                *reinterpret_cast<float2*>(op + col) = o;
            }
        }
    }
}

// ---------------------------------------------------------------------------
// Inputs: 0:x 1:k 2:l_t 3:s 4:aux_U 5:aux_Unp1 6:aux_Vt 7:aux_Vtnp1
//         8:b 9:aux_b 10:step
// ---------------------------------------------------------------------------
extern "C" void kernel_launch(void* const* d_in, const int* in_sizes, int n_in,
                              void* d_out, int out_size) {
    const float* x         = (const float*)d_in[0];
    const float* k_        = (const float*)d_in[1];
    const float* l_t       = (const float*)d_in[2];
    const float* s         = (const float*)d_in[3];
    const float* aux_U     = (const float*)d_in[4];
    const float* aux_Unp1  = (const float*)d_in[5];
    const float* aux_Vt    = (const float*)d_in[6];
    const float* aux_Vtnp1 = (const float*)d_in[7];
    const float* bias_b    = (const float*)d_in[8];
    const float* bias_aux  = (const float*)d_in[9];
    const int*   step_p    = (const int*)d_in[10];
    float* out = (float*)d_out;

    build_T<<<(IN_DIM * RANKn + 255) / 256, 256>>>(k_, aux_U, aux_Unp1, s, step_p);
    build_Wh<<<(FILTERS * IN_DIM + 255) / 256, 256>>>(aux_Vt, l_t, aux_Vtnp1, step_p);
    convert_x<<<(XTOT / 8 + 255) / 256, 256>>>(x);

    static bool cfg_done = false;
    if (!cfg_done) {
        cudaFuncSetAttribute(conv_main,
                             cudaFuncAttributeMaxDynamicSharedMemorySize, SM_TOTAL);
        cfg_done = true;
    }
    dim3 grid((Bn * Hn * Wn) / CTA_M, FILTERS / CTA_N);   // (3136, 2)
    conv_main<<<grid, NT, SM_TOTAL>>>(bias_b, bias_aux, step_p, out);
}

// round 7
// speedup vs baseline: 6.5689x; 1.0638x over previous
#include <cuda_runtime.h>
#include <cuda_fp16.h>
#include <cstdint>

// Problem constants
#define Bn 8
#define Hn 224
#define Wn 224
#define Cn 64
#define IN_DIM 576
#define RANKn 100
#define FILTERS 256
#define HW 50176            // 224*224
#define XTOT (Bn * Hn * Wn * Cn)

// GEMM tiling: CTA 128x128, 4 warps (2M x 2N), warp tile 64x64
#define CTA_M 128
#define CTA_N 128
#define BK 64                         // one full 3x3 tap (64 ch)
#define NT 128
#define KITERS (IN_DIM / BK)          // 9
#define STAGE_BYTES 32768             // A 16KB + B 16KB (fp16)
#define NSTAGE 3
#define SM_TOTAL (NSTAGE * STAGE_BYTES)  // 96KB -> 2 CTAs/SM

// Scratch (device globals; no allocation allowed)
__device__ float  g_T[IN_DIM * RANKn];
__device__ __half g_Wh[FILTERS * IN_DIM];   // [n][k] fp16
__device__ __half g_xh[XTOT];               // x in fp16, same layout

// ---------------------------------------------------------------------------
__device__ __forceinline__ uint32_t smem_u32(const void* p) {
    uint32_t a;
    asm("{ .reg .u64 t; cvta.to.shared.u64 t, %1; cvt.u32.u64 %0, t; }"
        : "=r"(a) : "l"(p));
    return a;
}
#define CP_ASYNC_Z(d, s, sz) \
    asm volatile("cp.async.cg.shared.global [%0], [%1], 16, %2;" \
                 :: "r"(d), "l"(s), "r"(sz))
#define CP_ASYNC16(d, s) \
    asm volatile("cp.async.cg.shared.global [%0], [%1], 16;" :: "r"(d), "l"(s))
#define CP_COMMIT() asm volatile("cp.async.commit_group;" ::: "memory")
#define CP_WAIT(n)  asm volatile("cp.async.wait_group %0;" :: "n"(n) : "memory")

#define LDSM_X4(r0, r1, r2, r3, a) \
    asm volatile("ldmatrix.sync.aligned.m8n8.x4.shared.b16 {%0,%1,%2,%3}, [%4];" \
                 : "=r"(r0), "=r"(r1), "=r"(r2), "=r"(r3) : "r"(a))

#define MMA_F16(c, a, b0, b1)                                               \
    asm volatile("mma.sync.aligned.m16n8k16.row.col.f32.f16.f16.f32 "       \
                 "{%0,%1,%2,%3}, {%4,%5,%6,%7}, {%8,%9}, {%0,%1,%2,%3};"    \
                 : "+f"((c)[0]), "+f"((c)[1]), "+f"((c)[2]), "+f"((c)[3])   \
                 : "r"((a)[0]), "r"((a)[1]), "r"((a)[2]), "r"((a)[3]),      \
                   "r"(b0), "r"(b1))

// ---------------------------------------------------------------------------
// Prep kernels
// ---------------------------------------------------------------------------
__global__ void build_T(const float* __restrict__ k_,
                        const float* __restrict__ aux_U,
                        const float* __restrict__ aux_Unp1,
                        const float* __restrict__ s,
                        const int* __restrict__ step_p) {
    int idx = blockIdx.x * blockDim.x + threadIdx.x;
    if (idx >= IN_DIM * RANKn) return;
    int st = *step_p;
    float v;
    if (st == 0) v = k_[idx];
    else if (st == 1) v = aux_U[idx];
    else {
        int p = idx / RANKn, r = idx % RANKn;
        float acc = 0.f;
        #pragma unroll 4
        for (int q = 0; q < RANKn; ++q)
            acc += aux_Unp1[p * RANKn + q] * s[q * RANKn + r];
        v = acc;
    }
    g_T[idx] = v;
}

__global__ void build_Wh(const float* __restrict__ aux_Vt,
                         const float* __restrict__ l_t,
                         const float* __restrict__ aux_Vtnp1,
                         const int* __restrict__ step_p) {
    int idx = blockIdx.x * blockDim.x + threadIdx.x;
    if (idx >= FILTERS * IN_DIM) return;
    int st = *step_p;
    const float* V = (st == 0) ? aux_Vt : (st == 1) ? l_t : aux_Vtnp1;
    int n = idx / IN_DIM, k = idx % IN_DIM;
    float acc = 0.f;
    #pragma unroll 4
    for (int r = 0; r < RANKn; ++r)
        acc += g_T[k * RANKn + r] * V[r * FILTERS + n];
    g_Wh[idx] = __float2half_rn(acc);
}

__global__ void convert_x(const float* __restrict__ x) {
    int idx = blockIdx.x * blockDim.x + threadIdx.x;   // one per 8 floats
    if (idx >= XTOT / 8) return;
    const float4* xp = reinterpret_cast<const float4*>(x) + idx * 2;
    float4 v0 = xp[0], v1 = xp[1];
    __half2 h[4];
    h[0] = __float22half2_rn(make_float2(v0.x, v0.y));
    h[1] = __float22half2_rn(make_float2(v0.z, v0.w));
    h[2] = __float22half2_rn(make_float2(v1.x, v1.y));
    h[3] = __float22half2_rn(make_float2(v1.z, v1.w));
    *reinterpret_cast<uint4*>(g_xh + (size_t)idx * 8) =
        *reinterpret_cast<uint4*>(h);
}

// ---------------------------------------------------------------------------
// Main: fp16 mma.sync implicit-GEMM conv
// CTA: 128 pixels x 128 filters; 4 warps (2M x 2N), warp tile 64x64.
// 3-stage cp.async ring, one barrier per K-iter, 2 CTAs/SM.
// ---------------------------------------------------------------------------
__global__ void __launch_bounds__(NT, 2)
conv_main(const float* __restrict__ bias_b,
          const float* __restrict__ bias_aux,
          const int* __restrict__ step_p,
          float* __restrict__ out) {
    extern __shared__ __align__(128) char smem[];
    const int tid  = threadIdx.x;
    const int lane = tid & 31;
    const int wid  = tid >> 5;
    const int mwarp = wid >> 1;       // 0..1
    const int nwarp = wid & 1;        // 0..1
    const int Mbase = blockIdx.x * CTA_M;
    const int Nbase = blockIdx.y * CTA_N;
    const uint32_t sb = smem_u32(smem);

    // Loader geometry: chunk j = tid&7, row group rA = tid>>3 (0..15)
    const int jA  = tid & 7;
    const int rA  = tid >> 3;
    int hL[8], wL[8], bL[8];
    #pragma unroll
    for (int l = 0; l < 8; ++l) {
        int p = Mbase + l * 16 + rA;
        int bi = p / HW;
        int rem = p - bi * HW;
        hL[l] = rem / Wn;
        wL[l] = rem - hL[l] * Wn;
        bL[l] = bi;
    }

    float acc[4][8][4];
    #pragma unroll
    for (int mt = 0; mt < 4; ++mt)
        #pragma unroll
        for (int nt = 0; nt < 8; ++nt)
            #pragma unroll
            for (int q = 0; q < 4; ++q) acc[mt][nt][q] = 0.f;

    auto load_stage = [&](int ko) {
        const int stage = ko % NSTAGE;
        const int dh = ko / 3 - 1;
        const int dw = ko % 3 - 1;
        const uint32_t dA = sb + stage * STAGE_BYTES;
        #pragma unroll
        for (int l = 0; l < 8; ++l) {
            const int row = l * 16 + rA;
            const int hh = hL[l] + dh;
            const int ww = wL[l] + dw;
            const bool ok = ((unsigned)hh < (unsigned)Hn) &&
                            ((unsigned)ww < (unsigned)Wn);
            const __half* sp = ok
                ? g_xh + (((size_t)bL[l] * Hn + hh) * Wn + ww) * Cn + jA * 8
                : g_xh;
            CP_ASYNC_Z(dA + row * 128 + ((jA ^ (row & 7)) << 4), sp, ok ? 16u : 0u);
        }
        const int k0 = ko * BK;
        const uint32_t dB = dA + 16384;
        #pragma unroll
        for (int l = 0; l < 8; ++l) {
            const int n = l * 16 + rA;
            const __half* bs = g_Wh + (size_t)(Nbase + n) * IN_DIM + k0 + jA * 8;
            CP_ASYNC16(dB + n * 128 + ((jA ^ (n & 7)) << 4), bs);
        }
    };

    // Fragment addressing
    const int m7  = lane & 7;
    const int khA = lane >> 4;               // A chunk parity
    const int khB = (lane >> 3) & 1;         // B chunk parity
    const uint32_t arow = (uint32_t)(mwarp * 64 + (lane & 15)) * 128;
    const uint32_t brow = (uint32_t)(nwarp * 64 + ((lane >> 4) << 3) + m7) * 128;
    uint32_t coffA[4], coffB[4];
    #pragma unroll
    for (int ks = 0; ks < 4; ++ks) {
        coffA[ks] = (uint32_t)(((ks * 2 + khA) ^ m7) << 4);
        coffB[ks] = (uint32_t)(((ks * 2 + khB) ^ m7) << 4);
    }

    load_stage(0); CP_COMMIT();
    load_stage(1); CP_COMMIT();

    for (int ko = 0; ko < KITERS; ++ko) {
        if (ko < KITERS - 1) CP_WAIT(1);
        else                 CP_WAIT(0);
        __syncthreads();
        if (ko + 2 < KITERS) { load_stage(ko + 2); CP_COMMIT(); }

        const uint32_t As = sb + (ko % NSTAGE) * STAGE_BYTES;
        const uint32_t Bs = As + 16384;

        #pragma unroll
        for (int ks = 0; ks < 4; ++ks) {
            uint32_t bf[4][4];
            #pragma unroll
            for (int np = 0; np < 4; ++np)
                LDSM_X4(bf[np][0], bf[np][1], bf[np][2], bf[np][3],
                        Bs + brow + np * (16 * 128) + coffB[ks]);
            uint32_t a[4][4];
            #pragma unroll
            for (int mt = 0; mt < 4; ++mt)
                LDSM_X4(a[mt][0], a[mt][1], a[mt][2], a[mt][3],
                        As + arow + mt * (16 * 128) + coffA[ks]);
            #pragma unroll
            for (int mt = 0; mt < 4; ++mt)
                #pragma unroll
                for (int nt = 0; nt < 8; ++nt)
                    MMA_F16(acc[mt][nt], a[mt],
                            bf[nt >> 1][(nt & 1) * 2],
                            bf[nt >> 1][(nt & 1) * 2 + 1]);
        }
    }

    // Epilogue: bias + relu + store
    const float* bias = (*step_p == 2) ? bias_b : bias_aux;
    const int g  = lane >> 2;
    const int tq = lane & 3;
    #pragma unroll
    for (int mt = 0; mt < 4; ++mt) {
        const int r0 = Mbase + mwarp * 64 + mt * 16 + g;
        #pragma unroll
        for (int half = 0; half < 2; ++half) {
            const int r = r0 + half * 8;
            const int bi = r / HW;
            const int rr = r - bi * HW;
            const float* bp = bias + (size_t)rr * FILTERS;
            float* op = out + (size_t)r * FILTERS;
            #pragma unroll
            for (int nt = 0; nt < 8; ++nt) {
                const int col = Nbase + nwarp * 64 + nt * 8 + tq * 2;
                const float2 bv = *reinterpret_cast<const float2*>(bp + col);
                float2 o;
                o.x = fmaxf(acc[mt][nt][half * 2 + 0] + bv.x, 0.f);
                o.y = fmaxf(acc[mt][nt][half * 2 + 1] + bv.y, 0.f);
                *reinterpret_cast<float2*>(op + col) = o;
            }
        }
    }
}

// ---------------------------------------------------------------------------
// Inputs: 0:x 1:k 2:l_t 3:s 4:aux_U 5:aux_Unp1 6:aux_Vt 7:aux_Vtnp1
//         8:b 9:aux_b 10:step
// ---------------------------------------------------------------------------
extern "C" void kernel_launch(void* const* d_in, const int* in_sizes, int n_in,
                              void* d_out, int out_size) {
    const float* x         = (const float*)d_in[0];
    const float* k_        = (const float*)d_in[1];
    const float* l_t       = (const float*)d_in[2];
    const float* s         = (const float*)d_in[3];
    const float* aux_U     = (const float*)d_in[4];
    const float* aux_Unp1  = (const float*)d_in[5];
    const float* aux_Vt    = (const float*)d_in[6];
    const float* aux_Vtnp1 = (const float*)d_in[7];
    const float* bias_b    = (const float*)d_in[8];
    const float* bias_aux  = (const float*)d_in[9];
    const int*   step_p    = (const int*)d_in[10];
    float* out = (float*)d_out;

    build_T<<<(IN_DIM * RANKn + 255) / 256, 256>>>(k_, aux_U, aux_Unp1, s, step_p);
    build_Wh<<<(FILTERS * IN_DIM + 255) / 256, 256>>>(aux_Vt, l_t, aux_Vtnp1, step_p);
    convert_x<<<(XTOT / 8 + 255) / 256, 256>>>(x);

    static bool cfg_done = false;
    if (!cfg_done) {
        cudaFuncSetAttribute(conv_main,
                             cudaFuncAttributeMaxDynamicSharedMemorySize, SM_TOTAL);
        cfg_done = true;
    }
    dim3 grid((Bn * Hn * Wn) / CTA_M, FILTERS / CTA_N);   // (3136, 2)
    conv_main<<<grid, NT, SM_TOTAL>>>(bias_b, bias_aux, step_p, out);
}